// round 1
// baseline (speedup 1.0000x reference)
#include <cuda_runtime.h>
#include <cuda_bf16.h>
#include <math.h>

#define HWD 36864
#define BD 4
#define QD 256
#define ED 128
#define SPLITS 16
#define KS (HWD / SPLITS)   // 2304
#define BK 32
#define KTILES (KS / BK)    // 72

// ---------------- static scratch (no dynamic allocation allowed) ----------------
__device__ __align__(16) __nv_bfloat16 g_pos[(size_t)BD * QD * HWD];
__device__ __align__(16) __nv_bfloat16 g_neg[(size_t)BD * QD * HWD];
__device__ __align__(16) __nv_bfloat16 g_p  [(size_t)BD * QD * HWD];
__device__ __align__(16) __nv_bfloat16 g_tgt[(size_t)BD * ED * HWD];
__device__ __align__(16) __nv_bfloat16 g_seg[(size_t)BD * ED * HWD];
__device__ float g_negsum[BD * QD];
__device__ float g_psum  [BD * QD];
__device__ float g_segsum[BD * ED];
__device__ int   g_nnzp  [BD * ED];
__device__ float g_nnzf  [BD];
__device__ __align__(16) float g_Ppos[(size_t)BD * SPLITS * QD * ED];
__device__ __align__(16) float g_Pneg[(size_t)BD * SPLITS * QD * ED];
__device__ __align__(16) float g_Pp  [(size_t)BD * SPLITS * QD * ED];

// ---------------- phase 1: per-(b,q) elementwise prep + row sums ----------------
__global__ __launch_bounds__(256) void prep_q_kernel(
    const float* __restrict__ ml, const float* __restrict__ pm,
    const float* __restrict__ pl)
{
    const int bq = blockIdx.x;             // b*QD + q
    const size_t base = (size_t)bq * HWD;
    const float4* ml4 = (const float4*)(ml + base);
    const float4* pm4 = (const float4*)(pm + base);
    const float4* pl4 = (const float4*)(pl + base);
    __nv_bfloat162* pos2 = (__nv_bfloat162*)(g_pos + base);
    __nv_bfloat162* neg2 = (__nv_bfloat162*)(g_neg + base);
    __nv_bfloat162* p2   = (__nv_bfloat162*)(g_p   + base);

    float ns = 0.f, ps = 0.f;
    for (int i = threadIdx.x; i < HWD / 4; i += 256) {
        float4 m = ml4[i], w = pm4[i], l = pl4[i];
        float mm[4] = {m.x, m.y, m.z, m.w};
        float ww[4] = {w.x, w.y, w.z, w.w};
        float ll[4] = {l.x, l.y, l.z, l.w};
        float pv[4], nv[4], qv[4];
#pragma unroll
        for (int j = 0; j < 4; j++) {
            float x = mm[j], wt = ww[j];
            float t = log1pf(__expf(-fabsf(x)));
            pv[j] = (t + fmaxf(-x, 0.f)) * wt;   // softplus(-x)*mask
            nv[j] = (t + fmaxf( x, 0.f)) * wt;   // softplus(x)*mask
            qv[j] = wt / (1.f + __expf(-ll[j])); // sigmoid*mask
            ns += nv[j];
            ps += qv[j];
        }
        pos2[i * 2]     = __floats2bfloat162_rn(pv[0], pv[1]);
        pos2[i * 2 + 1] = __floats2bfloat162_rn(pv[2], pv[3]);
        neg2[i * 2]     = __floats2bfloat162_rn(nv[0], nv[1]);
        neg2[i * 2 + 1] = __floats2bfloat162_rn(nv[2], nv[3]);
        p2[i * 2]       = __floats2bfloat162_rn(qv[0], qv[1]);
        p2[i * 2 + 1]   = __floats2bfloat162_rn(qv[2], qv[3]);
    }
    // deterministic block reduce
    __shared__ float smA[8], smB[8];
#pragma unroll
    for (int o = 16; o; o >>= 1) {
        ns += __shfl_xor_sync(0xffffffffu, ns, o);
        ps += __shfl_xor_sync(0xffffffffu, ps, o);
    }
    if ((threadIdx.x & 31) == 0) { smA[threadIdx.x >> 5] = ns; smB[threadIdx.x >> 5] = ps; }
    __syncthreads();
    if (threadIdx.x == 0) {
        float a = 0.f, b = 0.f;
#pragma unroll
        for (int i = 0; i < 8; i++) { a += smA[i]; b += smB[i]; }
        g_negsum[bq] = a;
        g_psum[bq]   = b;
    }
}

// ---------------- phase 2: per-(b,e) target prep + sums ----------------
__global__ __launch_bounds__(256) void prep_e_kernel(const float* __restrict__ seg)
{
    const int be = blockIdx.x;             // b*ED + e
    const size_t base = (size_t)be * HWD;
    const float4* s4 = (const float4*)(seg + base);
    __nv_bfloat162* tgt2 = (__nv_bfloat162*)(g_tgt + base);
    __nv_bfloat162* seg2 = (__nv_bfloat162*)(g_seg + base);

    float ss = 0.f;
    int cnt = 0;
    for (int i = threadIdx.x; i < HWD / 4; i += 256) {
        float4 s = s4[i];
        float sv[4] = {s.x, s.y, s.z, s.w};
        float tv[4];
#pragma unroll
        for (int j = 0; j < 4; j++) {
            bool on = sv[j] > 0.f;
            tv[j] = on ? 1.f : 0.f;
            cnt += on ? 1 : 0;
            ss += sv[j];
        }
        tgt2[i * 2]     = __floats2bfloat162_rn(tv[0], tv[1]);
        tgt2[i * 2 + 1] = __floats2bfloat162_rn(tv[2], tv[3]);
        seg2[i * 2]     = __floats2bfloat162_rn(sv[0], sv[1]);
        seg2[i * 2 + 1] = __floats2bfloat162_rn(sv[2], sv[3]);
    }
    __shared__ float smA[8];
    __shared__ int smC[8];
#pragma unroll
    for (int o = 16; o; o >>= 1) {
        ss  += __shfl_xor_sync(0xffffffffu, ss, o);
        cnt += __shfl_xor_sync(0xffffffffu, cnt, o);
    }
    if ((threadIdx.x & 31) == 0) { smA[threadIdx.x >> 5] = ss; smC[threadIdx.x >> 5] = cnt; }
    __syncthreads();
    if (threadIdx.x == 0) {
        float a = 0.f; int c = 0;
#pragma unroll
        for (int i = 0; i < 8; i++) { a += smA[i]; c += smC[i]; }
        g_segsum[be] = a;
        g_nnzp[be]   = c;
    }
}

__global__ void nnz_reduce_kernel()
{
    int b = blockIdx.x;                    // 4 blocks x 128 threads
    int v = g_nnzp[b * ED + threadIdx.x];
#pragma unroll
    for (int o = 16; o; o >>= 1) v += __shfl_xor_sync(0xffffffffu, v, o);
    __shared__ int sm[4];
    if ((threadIdx.x & 31) == 0) sm[threadIdx.x >> 5] = v;
    __syncthreads();
    if (threadIdx.x == 0) g_nnzf[b] = (float)(sm[0] + sm[1] + sm[2] + sm[3]);
}

// ---------------- phase 3: bf16 split-K GEMM, CTA tile 128x128 ----------------
__global__ __launch_bounds__(256) void gemm_kernel()
{
    int id = blockIdx.x;
    const int split = id & (SPLITS - 1); id >>= 4;
    const int mt  = id & 1;              id >>= 1;
    const int mat = id % 3;
    const int b   = id / 3;

    const __nv_bfloat16* Ab =
        (mat == 0 ? g_pos : mat == 1 ? g_neg : g_p) + (size_t)(b * QD + mt * 128) * HWD;
    const __nv_bfloat16* Bb =
        (mat < 2 ? g_tgt : g_seg) + (size_t)b * ED * HWD;
    float* Pout =
        (mat == 0 ? g_Ppos : mat == 1 ? g_Pneg : g_Pp) +
        ((size_t)(b * SPLITS + split) * QD + mt * 128) * ED;

    __shared__ __align__(16) __nv_bfloat16 As[2][128][BK + 8];
    __shared__ __align__(16) __nv_bfloat16 Bs[2][128][BK + 8];

    const int tid = threadIdx.x, lane = tid & 31, wid = tid >> 5;
    const int wm = wid & 1;       // 0..1 -> 64-row half
    const int wn = wid >> 1;      // 0..3 -> 32-col quarter
    const int k0 = split * KS;

    float acc[4][4][4];
#pragma unroll
    for (int mi = 0; mi < 4; mi++)
#pragma unroll
        for (int ni = 0; ni < 4; ni++)
#pragma unroll
            for (int c = 0; c < 4; c++) acc[mi][ni][c] = 0.f;

#define LOADTILE(kt, bufl) do {                                               \
        int kp = k0 + (kt) * BK;                                              \
        _Pragma("unroll")                                                     \
        for (int i_ = 0; i_ < 2; i_++) {                                      \
            int c_ = tid + i_ * 256;                                          \
            int row_ = c_ >> 2, col_ = (c_ & 3) * 8;                          \
            unsigned da_ = (unsigned)__cvta_generic_to_shared(&As[bufl][row_][col_]); \
            asm volatile("cp.async.ca.shared.global [%0], [%1], 16;\n"        \
                         :: "r"(da_), "l"(Ab + (size_t)row_ * HWD + kp + col_)); \
            unsigned db_ = (unsigned)__cvta_generic_to_shared(&Bs[bufl][row_][col_]); \
            asm volatile("cp.async.ca.shared.global [%0], [%1], 16;\n"        \
                         :: "r"(db_), "l"(Bb + (size_t)row_ * HWD + kp + col_)); \
        }                                                                     \
        asm volatile("cp.async.commit_group;\n");                             \
    } while (0)

    LOADTILE(0, 0);
    int buf = 0;
    for (int kt = 0; kt < KTILES; kt++) {
        if (kt + 1 < KTILES) {
            LOADTILE(kt + 1, buf ^ 1);
            asm volatile("cp.async.wait_group 1;\n");
        } else {
            asm volatile("cp.async.wait_group 0;\n");
        }
        __syncthreads();
#pragma unroll
        for (int s = 0; s < 2; s++) {
            const int ks = s * 16;
            unsigned af[4][4];
#pragma unroll
            for (int mi = 0; mi < 4; mi++) {
                unsigned addr = (unsigned)__cvta_generic_to_shared(
                    &As[buf][wm * 64 + mi * 16 + (lane & 15)][ks + ((lane >> 4) << 3)]);
                asm volatile("ldmatrix.sync.aligned.m8n8.x4.shared.b16 {%0,%1,%2,%3},[%4];"
                             : "=r"(af[mi][0]), "=r"(af[mi][1]), "=r"(af[mi][2]), "=r"(af[mi][3])
                             : "r"(addr));
            }
            unsigned bfr[4][2];
#pragma unroll
            for (int ni = 0; ni < 4; ni++) {
                int l = lane & 15;
                unsigned addr = (unsigned)__cvta_generic_to_shared(
                    &Bs[buf][wn * 32 + ni * 8 + (l & 7)][ks + ((l >> 3) << 3)]);
                asm volatile("ldmatrix.sync.aligned.m8n8.x2.shared.b16 {%0,%1},[%2];"
                             : "=r"(bfr[ni][0]), "=r"(bfr[ni][1]) : "r"(addr));
            }
#pragma unroll
            for (int mi = 0; mi < 4; mi++)
#pragma unroll
                for (int ni = 0; ni < 4; ni++)
                    asm volatile(
                        "mma.sync.aligned.m16n8k16.row.col.f32.bf16.bf16.f32 "
                        "{%0,%1,%2,%3},{%4,%5,%6,%7},{%8,%9},{%0,%1,%2,%3};\n"
                        : "+f"(acc[mi][ni][0]), "+f"(acc[mi][ni][1]),
                          "+f"(acc[mi][ni][2]), "+f"(acc[mi][ni][3])
                        : "r"(af[mi][0]), "r"(af[mi][1]), "r"(af[mi][2]), "r"(af[mi][3]),
                          "r"(bfr[ni][0]), "r"(bfr[ni][1]));
        }
        __syncthreads();
        buf ^= 1;
    }
#undef LOADTILE

#pragma unroll
    for (int mi = 0; mi < 4; mi++) {
        int r0 = wm * 64 + mi * 16 + (lane >> 2);
#pragma unroll
        for (int ni = 0; ni < 4; ni++) {
            int cc = wn * 32 + ni * 8 + (lane & 3) * 2;
            *(float2*)&Pout[(size_t)r0 * ED + cc]       = make_float2(acc[mi][ni][0], acc[mi][ni][1]);
            *(float2*)&Pout[(size_t)(r0 + 8) * ED + cc] = make_float2(acc[mi][ni][2], acc[mi][ni][3]);
        }
    }
}

// ---------------- phase 4: split-K reduce + cost assembly ----------------
__global__ __launch_bounds__(256) void epilogue_kernel(
    const float* __restrict__ positions, const float* __restrict__ true_positions,
    const float* __restrict__ iel, float* __restrict__ out)
{
    int idx = blockIdx.x * 256 + threadIdx.x;   // 0..BD*QD*ED-1
    int e = idx & (ED - 1);
    int q = (idx >> 7) & (QD - 1);
    int b = idx >> 15;

    size_t poff = (size_t)(b * SPLITS) * (QD * ED) + (size_t)q * ED + e;
    float gp = 0.f, gn = 0.f, gd = 0.f;
#pragma unroll
    for (int s = 0; s < SPLITS; s++) {
        size_t o = poff + (size_t)s * (QD * ED);
        gp += g_Ppos[o];
        gn += g_Pneg[o];
        gd += g_Pp[o];
    }

    float bce  = (gp + g_negsum[b * QD + q] - gn) / g_nnzf[b];
    float dice = 1.f - (2.f * gd + 1.f) /
                       (g_psum[b * QD + q] + g_segsum[b * ED + e] + 1.f);

    float x = iel[b * QD + q];
    float cls = log1pf(__expf(-fabsf(x))) + fmaxf(-x, 0.f); // softplus(-x)

    float px = positions[(b * QD + q) * 2 + 0];
    float py = positions[(b * QD + q) * 2 + 1];
    float tx = true_positions[(b * ED + e) * 2 + 0];
    float ty = true_positions[(b * ED + e) * 2 + 1];
    float ax = fabsf(px - tx), ay = fabsf(py - ty);
    float hx = ax < 1.f ? 0.5f * ax * ax : ax - 0.5f;
    float hy = ay < 1.f ? 0.5f * ay * ay : ay - 0.5f;
    float dist = 0.5f * (hx + hy);

    out[idx] = cls + bce + dice + dist;
}

// ---------------- launch ----------------
extern "C" void kernel_launch(void* const* d_in, const int* in_sizes, int n_in,
                              void* d_out, int out_size)
{
    const float* mask_logits    = (const float*)d_in[0];
    const float* pred_mask      = (const float*)d_in[1];
    const float* portion_logits = (const float*)d_in[2];
    const float* segmap         = (const float*)d_in[3];
    const float* positions      = (const float*)d_in[4];
    const float* true_positions = (const float*)d_in[5];
    const float* iel            = (const float*)d_in[6];
    float* out = (float*)d_out;

    prep_q_kernel<<<BD * QD, 256>>>(mask_logits, pred_mask, portion_logits);
    prep_e_kernel<<<BD * ED, 256>>>(segmap);
    nnz_reduce_kernel<<<BD, 128>>>();
    gemm_kernel<<<BD * 3 * 2 * SPLITS, 256>>>();
    epilogue_kernel<<<(BD * QD * ED) / 256, 256>>>(positions, true_positions, iel, out);
}